// round 3
// baseline (speedup 1.0000x reference)
#include <cuda_runtime.h>
#include <cuda_bf16.h>
#include <cstdint>
#include <cstddef>

#define DEV __device__ __forceinline__

namespace {
constexpr int Bb = 8, F = 8192, NL = 64, D = 1024, INNER = 512, H = 8, DH = 64;
constexpr int FN = F + NL;                 // 8256
constexpr int ROWS_X = Bb * F;             // 65536
constexpr int ROWS_L = Bb * NL;            // 512
constexpr int ROWS_KV = Bb * FN;           // 66048
constexpr float LN_EPS = 1e-5f;
constexpr float QSCALE = 0.125f;           // 64^-0.5
constexpr int SPLITS = 8;
constexpr int SPLEN = FN / SPLITS;         // 1032
}

// ------------------- device scratch (static: no allocations allowed) -------------------
__device__ float g_mu[ROWS_X];
__device__ float g_rstd[ROWS_X];
__device__ float g_latln[ROWS_L * D];
__device__ float g_bcat[D * 1024];                // gamma-folded [Wk | Wv]
__device__ float g_csum[1024];                    // colsum(gamma*W)
__device__ float g_bsum[1024];                    // colsum(beta*W)
__device__ float g_q[ROWS_L * INNER];
__device__ float g_k[(size_t)ROWS_KV * INNER];
__device__ float g_v[(size_t)ROWS_KV * INNER];
__device__ float g_y[ROWS_L * INNER];
__device__ float g_pm[Bb * H * SPLITS * NL];
__device__ float g_pl[Bb * H * SPLITS * NL];
__device__ float g_po[(size_t)Bb * H * SPLITS * NL * DH];

// ------------------- helpers -------------------
DEV unsigned f2tf(float x) {
    unsigned u;
    asm("cvt.rna.tf32.f32 %0, %1;" : "=r"(u) : "f"(x));
    return u;
}

DEV void mma_tf32(float c[4], const unsigned a[4], const unsigned b[2]) {
    asm volatile(
        "mma.sync.aligned.m16n8k8.row.col.f32.tf32.tf32.f32 "
        "{%0,%1,%2,%3},{%4,%5,%6,%7},{%8,%9},{%0,%1,%2,%3};\n"
        : "+f"(c[0]), "+f"(c[1]), "+f"(c[2]), "+f"(c[3])
        : "r"(a[0]), "r"(a[1]), "r"(a[2]), "r"(a[3]), "r"(b[0]), "r"(b[1]));
}

// ------------------- 1) per-row mean / rstd of x -------------------
__global__ void __launch_bounds__(128) stats_x_kernel(const float* __restrict__ x) {
    int r = blockIdx.x;
    const float4* xr = (const float4*)(x + (size_t)r * D);
    int t = threadIdx.x;
    float4 a = xr[t];
    float4 b = xr[t + 128];
    float s  = a.x + a.y + a.z + a.w + b.x + b.y + b.z + b.w;
    float ss = a.x * a.x + a.y * a.y + a.z * a.z + a.w * a.w
             + b.x * b.x + b.y * b.y + b.z * b.z + b.w * b.w;
    #pragma unroll
    for (int o = 16; o; o >>= 1) {
        s  += __shfl_xor_sync(0xffffffffu, s, o);
        ss += __shfl_xor_sync(0xffffffffu, ss, o);
    }
    __shared__ float sh[8];
    int w = t >> 5;
    if ((t & 31) == 0) { sh[w] = s; sh[w + 4] = ss; }
    __syncthreads();
    if (t == 0) {
        s  = sh[0] + sh[1] + sh[2] + sh[3];
        ss = sh[4] + sh[5] + sh[6] + sh[7];
        float mu = s * (1.f / D);
        float var = ss * (1.f / D) - mu * mu;
        g_mu[r] = mu;
        g_rstd[r] = rsqrtf(var + LN_EPS);
    }
}

// ------------------- 2) latent layernorm -------------------
__global__ void __launch_bounds__(256) ln_lat_kernel(const float* __restrict__ lat,
                                                     const float* __restrict__ gl,
                                                     const float* __restrict__ bl) {
    int r = blockIdx.x;
    int t = threadIdx.x;
    const float4* xr = (const float4*)(lat + (size_t)r * D);
    float4 a = xr[t];
    float s  = a.x + a.y + a.z + a.w;
    float ss = a.x * a.x + a.y * a.y + a.z * a.z + a.w * a.w;
    #pragma unroll
    for (int o = 16; o; o >>= 1) {
        s  += __shfl_xor_sync(0xffffffffu, s, o);
        ss += __shfl_xor_sync(0xffffffffu, ss, o);
    }
    __shared__ float sh[18];
    int w = t >> 5;
    if ((t & 31) == 0) { sh[w] = s; sh[8 + w] = ss; }
    __syncthreads();
    if (t == 0) {
        s = 0.f; ss = 0.f;
        #pragma unroll
        for (int i = 0; i < 8; i++) { s += sh[i]; ss += sh[8 + i]; }
        float mu = s * (1.f / D);
        float var = ss * (1.f / D) - mu * mu;
        sh[16] = mu;
        sh[17] = rsqrtf(var + LN_EPS);
    }
    __syncthreads();
    float mu = sh[16], rs = sh[17];
    float4 g4 = ((const float4*)gl)[t];
    float4 b4 = ((const float4*)bl)[t];
    float4 o;
    o.x = (a.x - mu) * rs * g4.x + b4.x;
    o.y = (a.y - mu) * rs * g4.y + b4.y;
    o.z = (a.z - mu) * rs * g4.z + b4.z;
    o.w = (a.w - mu) * rs * g4.w + b4.w;
    ((float4*)(g_latln + (size_t)r * D))[t] = o;
}

// ------------------- 3) weight prep: Bcat = gamma * [Wk|Wv], colsums -------------------
__global__ void __launch_bounds__(256) prep_bcat(const float* __restrict__ Wk,
                                                 const float* __restrict__ Wv,
                                                 const float* __restrict__ gm) {
    int d = blockIdx.x;
    float g = gm[d];
    for (int j = threadIdx.x; j < 1024; j += 256) {
        float w = (j < 512) ? Wk[(size_t)d * 512 + j] : Wv[(size_t)d * 512 + (j - 512)];
        g_bcat[(size_t)d * 1024 + j] = g * w;
    }
}

__global__ void __launch_bounds__(256) prep_colsums(const float* __restrict__ Wk,
                                                    const float* __restrict__ Wv,
                                                    const float* __restrict__ bm) {
    int j = blockIdx.x * 256 + threadIdx.x;   // 0..1023
    float cs = 0.f, bs = 0.f;
    for (int d = 0; d < 1024; d++) {
        cs += g_bcat[(size_t)d * 1024 + j];
        float w = (j < 512) ? Wk[(size_t)d * 512 + j] : Wv[(size_t)d * 512 + (j - 512)];
        bs += bm[d] * w;
    }
    g_csum[j] = cs;
    g_bsum[j] = bs;
}

// ------------------- 4) big fused K/V GEMM (tf32 mma, LN epilogue) -------------------
// C[65536 x 1024] = x @ Bcat ; epilogue: rstd*(acc - mu*csum) + bsum -> g_k / g_v
__global__ void __launch_bounds__(256) gemm_kv(const float* __restrict__ x) {
    extern __shared__ unsigned smem_[];
    unsigned* As = smem_;                    // [2][128*33]
    unsigned* Bs = smem_ + 2 * 128 * 33;     // [2][32*132]
    const int tid = threadIdx.x, warp = tid >> 5, lane = tid & 31;
    const int g = lane >> 2, tg = lane & 3;
    const int wm = warp >> 2, wn = warp & 3;
    const int m0 = blockIdx.y * 128, n0 = blockIdx.x * 128;

    float acc[4][4][4];
    #pragma unroll
    for (int a = 0; a < 4; a++)
        #pragma unroll
        for (int b = 0; b < 4; b++)
            #pragma unroll
            for (int c = 0; c < 4; c++) acc[a][b][c] = 0.f;

    const int ar = tid >> 3;          // + i*32
    const int ac = (tid & 7) * 4;
    const int br = tid >> 5;          // + i*8
    const int bc = (tid & 31) * 4;

    float4 pa[4], pb[4];
    #pragma unroll
    for (int i = 0; i < 4; i++)
        pa[i] = *reinterpret_cast<const float4*>(x + (size_t)(m0 + ar + i * 32) * 1024 + ac);
    #pragma unroll
    for (int i = 0; i < 4; i++)
        pb[i] = *reinterpret_cast<const float4*>(g_bcat + (size_t)(br + i * 8) * 1024 + n0 + bc);
    #pragma unroll
    for (int i = 0; i < 4; i++) {
        unsigned* p = As + (ar + i * 32) * 33 + ac;
        p[0] = f2tf(pa[i].x); p[1] = f2tf(pa[i].y); p[2] = f2tf(pa[i].z); p[3] = f2tf(pa[i].w);
    }
    #pragma unroll
    for (int i = 0; i < 4; i++) {
        unsigned* p = Bs + (br + i * 8) * 132 + bc;
        p[0] = f2tf(pb[i].x); p[1] = f2tf(pb[i].y); p[2] = f2tf(pb[i].z); p[3] = f2tf(pb[i].w);
    }
    __syncthreads();

    int cur = 0;
    for (int kt = 0; kt < 32; kt++) {
        if (kt < 31) {
            int k0 = (kt + 1) * 32;
            #pragma unroll
            for (int i = 0; i < 4; i++)
                pa[i] = *reinterpret_cast<const float4*>(x + (size_t)(m0 + ar + i * 32) * 1024 + k0 + ac);
            #pragma unroll
            for (int i = 0; i < 4; i++)
                pb[i] = *reinterpret_cast<const float4*>(g_bcat + (size_t)(k0 + br + i * 8) * 1024 + n0 + bc);
        }
        const unsigned* A_ = As + cur * (128 * 33);
        const unsigned* B_ = Bs + cur * (32 * 132);
        #pragma unroll
        for (int ks = 0; ks < 4; ks++) {
            const int k = ks * 8;
            unsigned af[4][4], bf[4][2];
            #pragma unroll
            for (int mf = 0; mf < 4; mf++) {
                const int r = wm * 64 + mf * 16;
                af[mf][0] = A_[(r + g) * 33 + k + tg];
                af[mf][1] = A_[(r + g + 8) * 33 + k + tg];
                af[mf][2] = A_[(r + g) * 33 + k + tg + 4];
                af[mf][3] = A_[(r + g + 8) * 33 + k + tg + 4];
            }
            #pragma unroll
            for (int nf = 0; nf < 4; nf++) {
                const int c = wn * 32 + nf * 8;
                bf[nf][0] = B_[(k + tg) * 132 + c + g];
                bf[nf][1] = B_[(k + tg + 4) * 132 + c + g];
            }
            #pragma unroll
            for (int mf = 0; mf < 4; mf++)
                #pragma unroll
                for (int nf = 0; nf < 4; nf++)
                    mma_tf32(acc[mf][nf], af[mf], bf[nf]);
        }
        if (kt < 31) {
            cur ^= 1;
            unsigned* Aw = As + cur * (128 * 33);
            unsigned* Bw = Bs + cur * (32 * 132);
            #pragma unroll
            for (int i = 0; i < 4; i++) {
                unsigned* p = Aw + (ar + i * 32) * 33 + ac;
                p[0] = f2tf(pa[i].x); p[1] = f2tf(pa[i].y); p[2] = f2tf(pa[i].z); p[3] = f2tf(pa[i].w);
            }
            #pragma unroll
            for (int i = 0; i < 4; i++) {
                unsigned* p = Bw + (br + i * 8) * 132 + bc;
                p[0] = f2tf(pb[i].x); p[1] = f2tf(pb[i].y); p[2] = f2tf(pb[i].z); p[3] = f2tf(pb[i].w);
            }
            __syncthreads();
        }
    }

    // epilogue: fold layernorm, split K / V, remap rows b*8192+fi -> b*8256+fi
    #pragma unroll
    for (int mf = 0; mf < 4; mf++) {
        int r0 = m0 + wm * 64 + mf * 16 + g;
        int r1 = r0 + 8;
        float mu0 = g_mu[r0], rs0 = g_rstd[r0];
        float mu1 = g_mu[r1], rs1 = g_rstd[r1];
        size_t ro0 = (size_t)((r0 >> 13) * 8256 + (r0 & 8191));
        size_t ro1 = (size_t)((r1 >> 13) * 8256 + (r1 & 8191));
        #pragma unroll
        for (int nf = 0; nf < 4; nf++) {
            int c0 = n0 + wn * 32 + nf * 8 + 2 * tg;
            #pragma unroll
            for (int jj = 0; jj < 2; jj++) {
                int j = c0 + jj;
                float cs = g_csum[j], bs2 = g_bsum[j];
                float v0 = rs0 * (acc[mf][nf][jj] - mu0 * cs) + bs2;
                float v1 = rs1 * (acc[mf][nf][2 + jj] - mu1 * cs) + bs2;
                if (j < 512) {
                    g_k[ro0 * 512 + j] = v0;
                    g_k[ro1 * 512 + j] = v1;
                } else {
                    g_v[ro0 * 512 + (j - 512)] = v0;
                    g_v[ro1 * 512 + (j - 512)] = v1;
                }
            }
        }
    }
}

// ------------------- 5) latent Q/K/V GEMM (fp32 FFMA, small) -------------------
// N-order: [Wq cols 0..511 | Wk 512..1023 | Wv 1024..1535]
__global__ void __launch_bounds__(256) gemm_lat(const float* __restrict__ Wq,
                                                const float* __restrict__ Wk,
                                                const float* __restrict__ Wv,
                                                const float* __restrict__ kvg) {
    __shared__ float as_[64][17];
    __shared__ float bs_[16][65];
    int t = threadIdx.x;
    int n0 = blockIdx.x * 64, m0 = blockIdx.y * 64;
    int w = n0 >> 9;
    int nj0 = n0 & 511;
    const float* W = (w == 0) ? Wq : ((w == 1) ? Wk : Wv);
    int tx = t & 15, ty = t >> 4;
    float c[4][4] = {};
    for (int k0 = 0; k0 < 1024; k0 += 16) {
        #pragma unroll
        for (int i = 0; i < 4; i++) {
            int id = t + i * 256;
            as_[id >> 4][id & 15] = g_latln[(size_t)(m0 + (id >> 4)) * 1024 + k0 + (id & 15)];
        }
        #pragma unroll
        for (int i = 0; i < 4; i++) {
            int id = t + i * 256;
            bs_[id >> 6][id & 63] = W[(size_t)(k0 + (id >> 6)) * 512 + nj0 + (id & 63)];
        }
        __syncthreads();
        #pragma unroll
        for (int kk = 0; kk < 16; kk++) {
            float ra[4], rb[4];
            #pragma unroll
            for (int i = 0; i < 4; i++) ra[i] = as_[ty + 16 * i][kk];
            #pragma unroll
            for (int j = 0; j < 4; j++) rb[j] = bs_[kk][tx + 16 * j];
            #pragma unroll
            for (int i = 0; i < 4; i++)
                #pragma unroll
                for (int j = 0; j < 4; j++) c[i][j] += ra[i] * rb[j];
        }
        __syncthreads();
    }
    float gate = *kvg;
    #pragma unroll
    for (int i = 0; i < 4; i++)
        #pragma unroll
        for (int j = 0; j < 4; j++) {
            int m = m0 + ty + 16 * i;
            int J = n0 + tx + 16 * j;
            int b = m >> 6, li = m & 63;
            float v = c[i][j];
            if (w == 0) {
                g_q[(size_t)m * 512 + J] = v * QSCALE;
            } else if (w == 1) {
                g_k[((size_t)(b * 8256 + 8192 + li)) * 512 + (J - 512)] = v * gate;
            } else {
                g_v[((size_t)(b * 8256 + 8192 + li)) * 512 + (J - 1024)] = v * gate;
            }
        }
}

// ------------------- 6) split-KV flash attention (fp32, online softmax) -------------------
__global__ void __launch_bounds__(256) attn_kernel(const int* __restrict__ mask) {
    __shared__ float qs[64][65];
    __shared__ float ks[32][65];
    __shared__ float vs[32][65];
    __shared__ float ss[64][33];

    const int s = blockIdx.x, h = blockIdx.y, b = blockIdx.z;
    const int t = threadIdx.x;
    const int qr = t >> 2, part = t & 3;

    // load Q tile (64 x 64)
    #pragma unroll
    for (int i = 0; i < 4; i++) {
        int id = t + i * 256;               // 1024 float4
        int r = id >> 4, c4 = id & 15;
        float4 q4 = *reinterpret_cast<const float4*>(
            g_q + (size_t)(b * 64 + r) * 512 + h * 64 + c4 * 4);
        qs[r][c4 * 4 + 0] = q4.x; qs[r][c4 * 4 + 1] = q4.y;
        qs[r][c4 * 4 + 2] = q4.z; qs[r][c4 * 4 + 3] = q4.w;
    }

    float m = -1e30f, l = 0.f;
    float acc[16];
    #pragma unroll
    for (int i = 0; i < 16; i++) acc[i] = 0.f;

    const int base = s * SPLEN;
    for (int k0 = 0; k0 < SPLEN; k0 += 32) {
        int nrows = min(32, SPLEN - k0);
        __syncthreads();
        // load K,V chunk (32 x 64 each)
        #pragma unroll
        for (int i = 0; i < 2; i++) {
            int id = t + i * 256;           // 512 float4
            int r = id >> 4, c4 = id & 15;
            if (r < nrows) {
                size_t ro = (size_t)(b * 8256 + base + k0 + r) * 512 + h * 64 + c4 * 4;
                float4 k4 = *reinterpret_cast<const float4*>(g_k + ro);
                float4 v4 = *reinterpret_cast<const float4*>(g_v + ro);
                ks[r][c4 * 4 + 0] = k4.x; ks[r][c4 * 4 + 1] = k4.y;
                ks[r][c4 * 4 + 2] = k4.z; ks[r][c4 * 4 + 3] = k4.w;
                vs[r][c4 * 4 + 0] = v4.x; vs[r][c4 * 4 + 1] = v4.y;
                vs[r][c4 * 4 + 2] = v4.z; vs[r][c4 * 4 + 3] = v4.w;
            } else {
                ks[r][c4 * 4 + 0] = 0.f; ks[r][c4 * 4 + 1] = 0.f;
                ks[r][c4 * 4 + 2] = 0.f; ks[r][c4 * 4 + 3] = 0.f;
                vs[r][c4 * 4 + 0] = 0.f; vs[r][c4 * 4 + 1] = 0.f;
                vs[r][c4 * 4 + 2] = 0.f; vs[r][c4 * 4 + 3] = 0.f;
            }
        }
        __syncthreads();
        // scores 64x32
        #pragma unroll
        for (int i = 0; i < 8; i++) {
            int id = t + i * 256;
            int qr2 = id >> 5, kr = id & 31;
            int pos = base + k0 + kr;
            bool valid = (kr < nrows) && (pos >= F || mask[b * F + pos] == 0);
            float sc = -1e30f;
            if (valid) {
                sc = 0.f;
                #pragma unroll 8
                for (int c = 0; c < 64; c++) sc += qs[qr2][c] * ks[kr][c];
            }
            ss[qr2][kr] = sc;
        }
        __syncthreads();
        // online softmax update (4 threads per q row; each owns 16 dh cols)
        float cmax = -1e30f;
        #pragma unroll
        for (int k = 0; k < 32; k++) cmax = fmaxf(cmax, ss[qr][k]);
        float mn = fmaxf(m, cmax);
        float scale = __expf(m - mn);
        m = mn;
        l *= scale;
        #pragma unroll
        for (int c = 0; c < 16; c++) acc[c] *= scale;
        float lsum = 0.f;
        #pragma unroll 4
        for (int k = 0; k < 32; k++) {
            float sck = ss[qr][k];
            float p = (sck > -1e29f) ? __expf(sck - mn) : 0.f;
            lsum += p;
            #pragma unroll
            for (int c = 0; c < 16; c++) acc[c] += p * vs[k][part * 16 + c];
        }
        l += lsum;
    }

    int idx = ((b * 8 + h) * 8 + s) * 64 + qr;
    if (part == 0) { g_pm[idx] = m; g_pl[idx] = l; }
    #pragma unroll
    for (int c = 0; c < 16; c++)
        g_po[(size_t)idx * 64 + part * 16 + c] = acc[c];
}

// ------------------- 7) split combine -> y -------------------
__global__ void __launch_bounds__(128) combine_kernel() {
    int bq = blockIdx.x;                 // 0..511 : b*64 + qr
    int b = bq >> 6, qr = bq & 63;
    int t = threadIdx.x;
    int h = t >> 4, c0 = (t & 15) * 4;
    int idx0 = ((b * 8 + h) * 8) * 64 + qr;   // stride 64 per split
    float M = -1e30f;
    #pragma unroll
    for (int s = 0; s < SPLITS; s++) M = fmaxf(M, g_pm[idx0 + s * 64]);
    float L = 0.f;
    float a[4] = {0.f, 0.f, 0.f, 0.f};
    #pragma unroll
    for (int s = 0; s < SPLITS; s++) {
        float w = __expf(g_pm[idx0 + s * 64] - M);
        L += g_pl[idx0 + s * 64] * w;
        size_t pb = (size_t)(idx0 + s * 64) * 64 + c0;
        #pragma unroll
        for (int j = 0; j < 4; j++) a[j] += g_po[pb + j] * w;
    }
    float inv = 1.f / L;
    size_t yo = (size_t)(b * 64 + qr) * 512 + h * 64 + c0;
    #pragma unroll
    for (int j = 0; j < 4; j++) g_y[yo + j] = a[j] * inv;
}

// ------------------- 8) output projection: out = y @ Wout -------------------
__global__ void __launch_bounds__(256) gemm_out(const float* __restrict__ Wout,
                                                float* __restrict__ out) {
    __shared__ float as_[64][17];
    __shared__ float bs_[16][65];
    int t = threadIdx.x;
    int n0 = blockIdx.x * 64, m0 = blockIdx.y * 64;
    int tx = t & 15, ty = t >> 4;
    float c[4][4] = {};
    for (int k0 = 0; k0 < 512; k0 += 16) {
        #pragma unroll
        for (int i = 0; i < 4; i++) {
            int id = t + i * 256;
            as_[id >> 4][id & 15] = g_y[(size_t)(m0 + (id >> 4)) * 512 + k0 + (id & 15)];
        }
        #pragma unroll
        for (int i = 0; i < 4; i++) {
            int id = t + i * 256;
            bs_[id >> 6][id & 63] = Wout[(size_t)(k0 + (id >> 6)) * 1024 + n0 + (id & 63)];
        }
        __syncthreads();
        #pragma unroll
        for (int kk = 0; kk < 16; kk++) {
            float ra[4], rb[4];
            #pragma unroll
            for (int i = 0; i < 4; i++) ra[i] = as_[ty + 16 * i][kk];
            #pragma unroll
            for (int j = 0; j < 4; j++) rb[j] = bs_[kk][tx + 16 * j];
            #pragma unroll
            for (int i = 0; i < 4; i++)
                #pragma unroll
                for (int j = 0; j < 4; j++) c[i][j] += ra[i] * rb[j];
        }
        __syncthreads();
    }
    #pragma unroll
    for (int i = 0; i < 4; i++)
        #pragma unroll
        for (int j = 0; j < 4; j++)
            out[(size_t)(m0 + ty + 16 * i) * 1024 + n0 + tx + 16 * j] = c[i][j];
}

// ------------------- launch -------------------
extern "C" void kernel_launch(void* const* d_in, const int* in_sizes, int n_in,
                              void* d_out, int out_size) {
    (void)in_sizes; (void)n_in; (void)out_size;
    const float* x   = (const float*)d_in[0];
    const float* lat = (const float*)d_in[1];
    const int*   mask = (const int*)d_in[2];          // bool -> int32 per harness contract
    const float* kvg = (const float*)d_in[3];
    const float* gm  = (const float*)d_in[4];
    const float* bm  = (const float*)d_in[5];
    const float* gl  = (const float*)d_in[6];
    const float* bl  = (const float*)d_in[7];
    const float* Wq  = (const float*)d_in[8];
    const float* Wk  = (const float*)d_in[9];
    const float* Wv  = (const float*)d_in[10];
    const float* Wout = (const float*)d_in[11];
    float* out = (float*)d_out;

    stats_x_kernel<<<ROWS_X, 128>>>(x);
    ln_lat_kernel<<<ROWS_L, 256>>>(lat, gl, bl);
    prep_bcat<<<1024, 256>>>(Wk, Wv, gm);
    prep_colsums<<<4, 256>>>(Wk, Wv, bm);

    cudaFuncSetAttribute(gemm_kv, cudaFuncAttributeMaxDynamicSharedMemorySize, 67584);
    gemm_kv<<<dim3(8, 512), 256, 67584>>>(x);

    gemm_lat<<<dim3(24, 8), 256>>>(Wq, Wk, Wv, kvg);
    attn_kernel<<<dim3(SPLITS, H, Bb), 256>>>(mask);
    combine_kernel<<<512, 128>>>();
    gemm_out<<<dim3(16, 8), 256>>>(Wout, out);
}